// round 1
// baseline (speedup 1.0000x reference)
#include <cuda_runtime.h>
#include <math.h>
#include <stdint.h>

// ---------------- problem constants ----------------
#define BATCH   8
#define SEQ     1024
#define M_ROWS  (BATCH*SEQ)        // 8192
#define D_MODEL 256
#define D_INNER 512
#define D_STATE 16
#define DT_RANK 16
#define N_LAYERS 4
#define W2V_DIM 768
#define LIB_DIM 93

// ---------------- scratch buffers (static device memory; no allocs) ----------------
__device__ float g_wl [M_ROWS * (2*D_MODEL)];   // concat(w2v_proj, lib_proj) [8192,512]
__device__ float g_t  [M_ROWS * D_MODEL];       // fuse output
__device__ float g_h  [M_ROWS * D_MODEL];       // residual stream
__device__ float g_xln[M_ROWS * D_MODEL];       // layernorm(h)
__device__ float g_xz [M_ROWS * (2*D_INNER)];   // in_proj output [8192,1024]
__device__ float g_xc [M_ROWS * D_INNER];       // conv+silu output
__device__ float g_dbl[M_ROWS * (DT_RANK+2*D_STATE)]; // xproj output [8192,48]
__device__ float g_dt [M_ROWS * D_INNER];       // softplus(dt)
__device__ float g_y  [M_ROWS * D_INNER];       // scan output

// ---------------- generic SGEMM: C[M,N] = A[M,K] @ W[N,K]^T (+bias)(+C) ----------------
// BM=128, BN=64, BK=16, 256 threads, TM=8, TN=4
template<bool ACC>
__global__ void gemm_k(const float* __restrict__ A, const float* __restrict__ W,
                       const float* __restrict__ bias, float* __restrict__ C,
                       int M, int N, int K, int ldc)
{
    const int BM = 128, BN = 64, BK = 16, TM = 8, TN = 4;
    __shared__ float As[BK][BM + 1];
    __shared__ float Ws[BK][BN + 1];

    int tid = threadIdx.x;
    int tx = tid & 15;          // 0..15 -> n
    int ty = tid >> 4;          // 0..15 -> m
    int m0 = blockIdx.y * BM;
    int n0 = blockIdx.x * BN;

    float acc[TM][TN];
#pragma unroll
    for (int i = 0; i < TM; i++)
#pragma unroll
        for (int j = 0; j < TN; j++) acc[i][j] = 0.f;

    int ntiles = (K + BK - 1) / BK;
    for (int kt = 0; kt < ntiles; kt++) {
        int k0 = kt * BK;
        // load A tile [BM x BK] transposed into As[k][m]
#pragma unroll
        for (int it = 0; it < (BM*BK)/256; it++) {
            int idx = tid + it * 256;
            int k = idx & (BK - 1);
            int m = idx >> 4;
            int gm = m0 + m, gk = k0 + k;
            float v = 0.f;
            if (gm < M && gk < K) v = A[(size_t)gm * K + gk];
            As[k][m] = v;
        }
        // load W tile [BN x BK] transposed into Ws[k][n]
#pragma unroll
        for (int it = 0; it < (BN*BK)/256; it++) {
            int idx = tid + it * 256;
            int k = idx & (BK - 1);
            int n = idx >> 4;
            int gn = n0 + n, gk = k0 + k;
            float v = 0.f;
            if (gn < N && gk < K) v = W[(size_t)gn * K + gk];
            Ws[k][n] = v;
        }
        __syncthreads();
#pragma unroll
        for (int k = 0; k < BK; k++) {
            float rm[TM], rn[TN];
#pragma unroll
            for (int i = 0; i < TM; i++) rm[i] = As[k][ty * TM + i];
#pragma unroll
            for (int j = 0; j < TN; j++) rn[j] = Ws[k][tx * TN + j];
#pragma unroll
            for (int i = 0; i < TM; i++)
#pragma unroll
                for (int j = 0; j < TN; j++)
                    acc[i][j] = fmaf(rm[i], rn[j], acc[i][j]);
        }
        __syncthreads();
    }

#pragma unroll
    for (int i = 0; i < TM; i++) {
        int m = m0 + ty * TM + i;
        if (m >= M) continue;
#pragma unroll
        for (int j = 0; j < TN; j++) {
            int n = n0 + tx * TN + j;
            if (n >= N) continue;
            float v = acc[i][j];
            if (bias) v += bias[n];
            size_t off = (size_t)m * ldc + n;
            if (ACC) v += C[off];
            C[off] = v;
        }
    }
}

// ---------------- layernorm (warp per row of 256) ----------------
__global__ void ln_k(const float* __restrict__ x, const float* __restrict__ g,
                     const float* __restrict__ b, float* __restrict__ y)
{
    int warp = (blockIdx.x * blockDim.x + threadIdx.x) >> 5;
    int lane = threadIdx.x & 31;
    if (warp >= M_ROWS) return;
    const float* xr = x + (size_t)warp * D_MODEL;
    float v[8];
    float s = 0.f, s2 = 0.f;
#pragma unroll
    for (int i = 0; i < 8; i++) {
        v[i] = xr[lane + i * 32];
        s += v[i];
        s2 = fmaf(v[i], v[i], s2);
    }
#pragma unroll
    for (int o = 16; o > 0; o >>= 1) {
        s  += __shfl_xor_sync(0xffffffffu, s,  o);
        s2 += __shfl_xor_sync(0xffffffffu, s2, o);
    }
    float mu = s * (1.f / D_MODEL);
    float var = s2 * (1.f / D_MODEL) - mu * mu;
    float inv = rsqrtf(var + 1e-5f);
    float* yr = y + (size_t)warp * D_MODEL;
#pragma unroll
    for (int i = 0; i < 8; i++) {
        int c = lane + i * 32;
        yr[c] = (v[i] - mu) * inv * g[c] + b[c];
    }
}

// ---------------- causal depthwise conv(4) + silu ----------------
__global__ void conv_k(const float* __restrict__ xz, const float* __restrict__ cw,
                       const float* __restrict__ cb, float* __restrict__ xc)
{
    int idx = blockIdx.x * blockDim.x + threadIdx.x;
    if (idx >= M_ROWS * D_INNER) return;
    int d = idx & (D_INNER - 1);
    int row = idx >> 9;
    int t = row & (SEQ - 1);
    size_t base = (size_t)row * (2*D_INNER) + d;
    float acc = cb[d];
    const float* w = cw + d * 4;
#pragma unroll
    for (int k = 0; k < 4; k++) {
        int tt = t - 3 + k;
        if (tt >= 0) acc = fmaf(xz[base + (size_t)(k - 3) * (2*D_INNER)], w[k], acc);
    }
    // silu
    float sig = 1.f / (1.f + __expf(-acc));
    xc[(size_t)row * D_INNER + d] = acc * sig;
}

// ---------------- dt = softplus(dbl[:, :16] @ dtW^T + dtb) ----------------
__global__ void dt_k(const float* __restrict__ dbl, const float* __restrict__ dtW,
                     const float* __restrict__ dtb, float* __restrict__ dt)
{
    int idx = blockIdx.x * blockDim.x + threadIdx.x;
    if (idx >= M_ROWS * D_INNER) return;
    int d = idx & (D_INNER - 1);
    int row = idx >> 9;
    const float* r = dbl + (size_t)row * 48;
    const float* w = dtW + d * DT_RANK;
    float s = dtb[d];
#pragma unroll
    for (int j = 0; j < DT_RANK; j++) s = fmaf(r[j], w[j], s);
    // softplus
    float sp = (s > 20.f) ? s : log1pf(__expf(s));
    dt[(size_t)row * D_INNER + d] = sp;
}

// ---------------- selective scan ----------------
// warp handles 8 channels of one batch; 4 lanes per channel, 4 states per lane.
// 512 warps total. Next-iteration loads are software-pipelined.
__global__ void scan_k(const float* __restrict__ dt, const float* __restrict__ xc,
                       const float* __restrict__ dbl, const float* __restrict__ xz,
                       const float* __restrict__ A_log, const float* __restrict__ Dv,
                       float* __restrict__ yb)
{
    int warp = (blockIdx.x * blockDim.x + threadIdx.x) >> 5;
    int lane = threadIdx.x & 31;
    if (warp >= BATCH * (D_INNER / 8)) return;
    int b = warp >> 6;              // 64 warps per batch
    int dgrp = warp & 63;
    int dl = lane >> 2;             // 0..7 channel within warp
    int sg = lane & 3;              // 4-state group
    int d = dgrp * 8 + dl;

    const float* pdt = dt  + (size_t)b * SEQ * D_INNER + d;
    const float* pxc = xc  + (size_t)b * SEQ * D_INNER + d;
    const float* pz  = xz  + (size_t)b * SEQ * (2*D_INNER) + D_INNER + d;
    const float* pbc = dbl + (size_t)b * SEQ * 48 + DT_RANK + 4 * sg;
    float* py        = yb  + (size_t)b * SEQ * D_INNER + d;

    float4 al = *(const float4*)(A_log + d * D_STATE + 4 * sg);
    float a0 = -expf(al.x), a1 = -expf(al.y), a2 = -expf(al.z), a3 = -expf(al.w);
    float Dd = Dv[d];

    float h0 = 0.f, h1 = 0.f, h2 = 0.f, h3 = 0.f;

    float dt_c = pdt[0];
    float xc_c = pxc[0];
    float z_c  = pz[0];
    float4 Bc = *(const float4*)(pbc);
    float4 Cc = *(const float4*)(pbc + D_STATE);

    for (int t = 0; t < SEQ; t++) {
        int tn = (t + 1 < SEQ) ? (t + 1) : t;
        float dt_n = pdt[(size_t)tn * D_INNER];
        float xc_n = pxc[(size_t)tn * D_INNER];
        float z_n  = pz[(size_t)tn * (2*D_INNER)];
        float4 B_n = *(const float4*)(pbc + (size_t)tn * 48);
        float4 C_n = *(const float4*)(pbc + (size_t)tn * 48 + D_STATE);

        float u = dt_c * xc_c;
        float e0 = __expf(dt_c * a0);
        float e1 = __expf(dt_c * a1);
        float e2 = __expf(dt_c * a2);
        float e3 = __expf(dt_c * a3);
        h0 = fmaf(h0, e0, u * Bc.x);
        h1 = fmaf(h1, e1, u * Bc.y);
        h2 = fmaf(h2, e2, u * Bc.z);
        h3 = fmaf(h3, e3, u * Bc.w);
        float y = h0 * Cc.x;
        y = fmaf(h1, Cc.y, y);
        y = fmaf(h2, Cc.z, y);
        y = fmaf(h3, Cc.w, y);
        y += __shfl_xor_sync(0xffffffffu, y, 1);
        y += __shfl_xor_sync(0xffffffffu, y, 2);
        float yy = fmaf(xc_c, Dd, y);
        float sz = z_c / (1.f + __expf(-z_c));   // silu(z)
        if (sg == 0) py[(size_t)t * D_INNER] = yy * sz;

        dt_c = dt_n; xc_c = xc_n; z_c = z_n; Bc = B_n; Cc = C_n;
    }
}

// ---------------- host side ----------------
static inline void launch_gemm(const float* A, const float* W, const float* bias,
                               float* C, int M, int N, int K, int ldc, bool acc)
{
    dim3 grid((N + 63) / 64, (M + 127) / 128);
    if (acc) gemm_k<true><<<grid, 256>>>(A, W, bias, C, M, N, K, ldc);
    else     gemm_k<false><<<grid, 256>>>(A, W, bias, C, M, N, K, ldc);
}

extern "C" void kernel_launch(void* const* d_in, const int* in_sizes, int n_in,
                              void* d_out, int out_size)
{
    const float* wav    = (const float*)d_in[0];
    const float* lib    = (const float*)d_in[1];
    const float* w2v_W  = (const float*)d_in[2];
    const float* w2v_b  = (const float*)d_in[3];
    const float* lib_W  = (const float*)d_in[4];
    const float* lib_b  = (const float*)d_in[5];
    const float* fuse_W = (const float*)d_in[6];
    const float* fuse_b = (const float*)d_in[7];
    const float* proj_W = (const float*)d_in[8];
    const float* proj_b = (const float*)d_in[9];
    const float* ln_g   = (const float*)d_in[10];
    const float* ln_b   = (const float*)d_in[11];
    const float* in_W   = (const float*)d_in[12];
    const float* conv_W = (const float*)d_in[13];
    const float* conv_b = (const float*)d_in[14];
    const float* xproj_W= (const float*)d_in[15];
    const float* dt_W   = (const float*)d_in[16];
    const float* dt_b   = (const float*)d_in[17];
    const float* A_log  = (const float*)d_in[18];
    const float* D_vec  = (const float*)d_in[19];
    const float* out_W  = (const float*)d_in[20];
    const float* fnorm_g= (const float*)d_in[21];
    const float* fnorm_b= (const float*)d_in[22];
    float* out = (float*)d_out;

    float *wl, *tb, *hb, *xln, *xzb, *xcb, *dblb, *dtb2, *yb;
    cudaGetSymbolAddress((void**)&wl,   g_wl);
    cudaGetSymbolAddress((void**)&tb,   g_t);
    cudaGetSymbolAddress((void**)&hb,   g_h);
    cudaGetSymbolAddress((void**)&xln,  g_xln);
    cudaGetSymbolAddress((void**)&xzb,  g_xz);
    cudaGetSymbolAddress((void**)&xcb,  g_xc);
    cudaGetSymbolAddress((void**)&dblb, g_dbl);
    cudaGetSymbolAddress((void**)&dtb2, g_dt);
    cudaGetSymbolAddress((void**)&yb,   g_y);

    const int M = M_ROWS;

    // frontend
    launch_gemm(wav, w2v_W, w2v_b, wl,        M, D_MODEL, W2V_DIM, 2*D_MODEL, false);
    launch_gemm(lib, lib_W, lib_b, wl + D_MODEL, M, D_MODEL, LIB_DIM, 2*D_MODEL, false);
    launch_gemm(wl,  fuse_W, fuse_b, tb,      M, D_MODEL, 2*D_MODEL, D_MODEL, false);
    launch_gemm(tb,  proj_W, proj_b, hb,      M, D_MODEL, D_MODEL,   D_MODEL, false);

    const int EW_BLOCKS = (M_ROWS * D_INNER) / 256;

    for (int i = 0; i < N_LAYERS; i++) {
        const float* lg  = ln_g   + i * D_MODEL;
        const float* lb  = ln_b   + i * D_MODEL;
        const float* iw  = in_W   + (size_t)i * 2*D_INNER * D_MODEL;
        const float* cw  = conv_W + (size_t)i * D_INNER * 4;
        const float* cb  = conv_b + (size_t)i * D_INNER;
        const float* xw  = xproj_W+ (size_t)i * (DT_RANK + 2*D_STATE) * D_INNER;
        const float* dw  = dt_W   + (size_t)i * D_INNER * DT_RANK;
        const float* db  = dt_b   + (size_t)i * D_INNER;
        const float* al  = A_log  + (size_t)i * D_INNER * D_STATE;
        const float* dv  = D_vec  + (size_t)i * D_INNER;
        const float* ow  = out_W  + (size_t)i * D_MODEL * D_INNER;

        ln_k<<<M_ROWS / 8, 256>>>(hb, lg, lb, xln);
        launch_gemm(xln, iw, nullptr, xzb, M, 2*D_INNER, D_MODEL, 2*D_INNER, false);
        conv_k<<<EW_BLOCKS, 256>>>(xzb, cw, cb, xcb);
        launch_gemm(xcb, xw, nullptr, dblb, M, DT_RANK + 2*D_STATE, D_INNER, DT_RANK + 2*D_STATE, false);
        dt_k<<<EW_BLOCKS, 256>>>(dblb, dw, db, dtb2);
        scan_k<<<128, 128>>>(dtb2, xcb, dblb, xzb, al, dv, yb);
        launch_gemm(yb, ow, nullptr, hb, M, D_MODEL, D_INNER, D_MODEL, true);
    }

    ln_k<<<M_ROWS / 8, 256>>>(hb, fnorm_g, fnorm_b, out);
}

// round 2
// speedup vs baseline: 1.6862x; 1.6862x over previous
#include <cuda_runtime.h>
#include <math.h>
#include <stdint.h>

// ---------------- problem constants ----------------
#define BATCH   8
#define SEQ     1024
#define M_ROWS  (BATCH*SEQ)        // 8192
#define D_MODEL 256
#define D_INNER 512
#define D_STATE 16
#define DT_RANK 16
#define N_LAYERS 4
#define W2V_DIM 768
#define LIB_DIM 93

// ---------------- scratch buffers ----------------
__device__ float g_wl [M_ROWS * (2*D_MODEL)];
__device__ float g_t  [M_ROWS * D_MODEL];
__device__ float g_h  [M_ROWS * D_MODEL];
__device__ float g_xln[M_ROWS * D_MODEL];
__device__ float g_xz [M_ROWS * (2*D_INNER)];
__device__ float g_xc [M_ROWS * D_INNER];
__device__ float g_dbl[M_ROWS * (DT_RANK+2*D_STATE)];
__device__ float g_dt [M_ROWS * D_INNER];
__device__ float g_y  [M_ROWS * D_INNER];

// ============================================================
// TF32 tensor-core GEMM:  C[M,N] = A[M,K] @ W[N,K]^T (+bias)(+=C)
// CTA tile 128x128, BK=16, 8 warps (2m x 4n), warp tile 64x32.
// M must be a multiple of 128 (true here: M = 8192 always).
// ============================================================
#define GBM 128
#define GBN 128
#define GBK 16
#define GPAD 20   // floats per smem row -> conflict-free fragment loads

__device__ __forceinline__ uint32_t f2tf(float f) {
    uint32_t u;
    asm("cvt.rna.tf32.f32 %0, %1;" : "=r"(u) : "f"(f));
    return u;
}

__device__ __forceinline__ void mma_tf32(float c[4], uint32_t a0, uint32_t a1,
                                         uint32_t a2, uint32_t a3,
                                         uint32_t b0, uint32_t b1) {
    asm volatile(
        "mma.sync.aligned.m16n8k8.row.col.f32.tf32.tf32.f32 "
        "{%0,%1,%2,%3}, {%4,%5,%6,%7}, {%8,%9}, {%0,%1,%2,%3};"
        : "+f"(c[0]), "+f"(c[1]), "+f"(c[2]), "+f"(c[3])
        : "r"(a0), "r"(a1), "r"(a2), "r"(a3), "r"(b0), "r"(b1));
}

template<bool ACC>
__global__ __launch_bounds__(256)
void gemm_tf32(const float* __restrict__ A, const float* __restrict__ W,
               const float* __restrict__ bias, float* __restrict__ C,
               int M, int N, int K, int ldc)
{
    __shared__ uint32_t As[2][GBM * GPAD];
    __shared__ uint32_t Ws[2][GBN * GPAD];

    const int tid  = threadIdx.x;
    const int lane = tid & 31;
    const int g    = lane >> 2;       // group 0..7
    const int tg   = lane & 3;        // thread-in-group 0..3
    const int warp = tid >> 5;
    const int wm   = warp >> 2;       // 0..1
    const int wn   = warp & 3;        // 0..3
    const int m0   = blockIdx.y * GBM;
    const int n0   = blockIdx.x * GBN;
    const bool k4  = (K & 3) == 0;

    float acc[4][4][4];
#pragma unroll
    for (int i = 0; i < 4; i++)
#pragma unroll
        for (int j = 0; j < 4; j++)
#pragma unroll
            for (int l = 0; l < 4; l++) acc[i][j][l] = 0.f;

    const int ntiles = (K + GBK - 1) / GBK;
    float4 vA[2], vW[2];

    // per-thread load coordinates (2 float4 slots per matrix)
    int rowA[2], colA[2], rowW[2], colW[2];
#pragma unroll
    for (int i = 0; i < 2; i++) {
        int id = tid + i * 256;
        rowA[i] = id >> 2; colA[i] = (id & 3) * 4;
        rowW[i] = id >> 2; colW[i] = (id & 3) * 4;
    }

    auto loadA = [&](int kt) {
        int k0 = kt * GBK;
#pragma unroll
        for (int i = 0; i < 2; i++) {
            int gm = m0 + rowA[i];
            int gk = k0 + colA[i];
            float4 v = make_float4(0.f, 0.f, 0.f, 0.f);
            const float* p = A + (size_t)gm * K + gk;
            if (k4 && gk + 3 < K) v = *(const float4*)p;
            else {
                if (gk     < K) v.x = p[0];
                if (gk + 1 < K) v.y = p[1];
                if (gk + 2 < K) v.z = p[2];
                if (gk + 3 < K) v.w = p[3];
            }
            vA[i] = v;
        }
    };
    auto loadW = [&](int kt) {
        int k0 = kt * GBK;
#pragma unroll
        for (int i = 0; i < 2; i++) {
            int gn = n0 + rowW[i];
            int gk = k0 + colW[i];
            float4 v = make_float4(0.f, 0.f, 0.f, 0.f);
            if (gn < N) {
                const float* p = W + (size_t)gn * K + gk;
                if (k4 && gk + 3 < K) v = *(const float4*)p;
                else {
                    if (gk     < K) v.x = p[0];
                    if (gk + 1 < K) v.y = p[1];
                    if (gk + 2 < K) v.z = p[2];
                    if (gk + 3 < K) v.w = p[3];
                }
            }
            vW[i] = v;
        }
    };
    auto store = [&](int buf) {
#pragma unroll
        for (int i = 0; i < 2; i++) {
            uint32_t* d = &As[buf][rowA[i] * GPAD + colA[i]];
            d[0] = f2tf(vA[i].x); d[1] = f2tf(vA[i].y);
            d[2] = f2tf(vA[i].z); d[3] = f2tf(vA[i].w);
            uint32_t* e = &Ws[buf][rowW[i] * GPAD + colW[i]];
            e[0] = f2tf(vW[i].x); e[1] = f2tf(vW[i].y);
            e[2] = f2tf(vW[i].z); e[3] = f2tf(vW[i].w);
        }
    };
    auto compute = [&](int buf) {
#pragma unroll
        for (int ks = 0; ks < 2; ks++) {
            int kk = ks * 8;
            uint32_t af[4][4], bf[4][2];
#pragma unroll
            for (int mt = 0; mt < 4; mt++) {
                int r = wm * 64 + mt * 16 + g;
                af[mt][0] = As[buf][(r    ) * GPAD + kk + tg    ];
                af[mt][1] = As[buf][(r + 8) * GPAD + kk + tg    ];
                af[mt][2] = As[buf][(r    ) * GPAD + kk + tg + 4];
                af[mt][3] = As[buf][(r + 8) * GPAD + kk + tg + 4];
            }
#pragma unroll
            for (int nt = 0; nt < 4; nt++) {
                int c = wn * 32 + nt * 8 + g;
                bf[nt][0] = Ws[buf][c * GPAD + kk + tg    ];
                bf[nt][1] = Ws[buf][c * GPAD + kk + tg + 4];
            }
#pragma unroll
            for (int mt = 0; mt < 4; mt++)
#pragma unroll
                for (int nt = 0; nt < 4; nt++)
                    mma_tf32(acc[mt][nt], af[mt][0], af[mt][1], af[mt][2], af[mt][3],
                             bf[nt][0], bf[nt][1]);
        }
    };

    loadA(0); loadW(0);
    store(0);
    __syncthreads();
    for (int kt = 0; kt < ntiles; kt++) {
        int buf = kt & 1;
        if (kt + 1 < ntiles) { loadA(kt + 1); loadW(kt + 1); }
        compute(buf);
        if (kt + 1 < ntiles) {
            store(buf ^ 1);
            __syncthreads();
        }
    }

    // epilogue
#pragma unroll
    for (int mt = 0; mt < 4; mt++) {
        int r0 = m0 + wm * 64 + mt * 16 + g;
#pragma unroll
        for (int nt = 0; nt < 4; nt++) {
            int c0 = n0 + wn * 32 + nt * 8 + 2 * tg;
#pragma unroll
            for (int half = 0; half < 2; half++) {
                int r = r0 + half * 8;
#pragma unroll
                for (int jj = 0; jj < 2; jj++) {
                    int c = c0 + jj;
                    if (c < N) {
                        float v = acc[mt][nt][half * 2 + jj];
                        if (bias) v += bias[c];
                        size_t off = (size_t)r * ldc + c;
                        if (ACC) v += C[off];
                        C[off] = v;
                    }
                }
            }
        }
    }
}

// ---------------- layernorm (warp per row of 256) ----------------
__global__ void ln_k(const float* __restrict__ x, const float* __restrict__ g,
                     const float* __restrict__ b, float* __restrict__ y)
{
    int warp = (blockIdx.x * blockDim.x + threadIdx.x) >> 5;
    int lane = threadIdx.x & 31;
    if (warp >= M_ROWS) return;
    const float* xr = x + (size_t)warp * D_MODEL;
    float v[8];
    float s = 0.f, s2 = 0.f;
#pragma unroll
    for (int i = 0; i < 8; i++) {
        v[i] = xr[lane + i * 32];
        s += v[i];
        s2 = fmaf(v[i], v[i], s2);
    }
#pragma unroll
    for (int o = 16; o > 0; o >>= 1) {
        s  += __shfl_xor_sync(0xffffffffu, s,  o);
        s2 += __shfl_xor_sync(0xffffffffu, s2, o);
    }
    float mu = s * (1.f / D_MODEL);
    float var = s2 * (1.f / D_MODEL) - mu * mu;
    float inv = rsqrtf(var + 1e-5f);
    float* yr = y + (size_t)warp * D_MODEL;
#pragma unroll
    for (int i = 0; i < 8; i++) {
        int c = lane + i * 32;
        yr[c] = (v[i] - mu) * inv * g[c] + b[c];
    }
}

// ---------------- causal depthwise conv(4) + silu ----------------
__global__ void conv_k(const float* __restrict__ xz, const float* __restrict__ cw,
                       const float* __restrict__ cb, float* __restrict__ xc)
{
    int idx = blockIdx.x * blockDim.x + threadIdx.x;
    if (idx >= M_ROWS * D_INNER) return;
    int d = idx & (D_INNER - 1);
    int row = idx >> 9;
    int t = row & (SEQ - 1);
    size_t base = (size_t)row * (2*D_INNER) + d;
    float acc = cb[d];
    const float* w = cw + d * 4;
#pragma unroll
    for (int k = 0; k < 4; k++) {
        int tt = t - 3 + k;
        if (tt >= 0) acc = fmaf(xz[base + (size_t)(k - 3) * (2*D_INNER)], w[k], acc);
    }
    float sig = 1.f / (1.f + __expf(-acc));
    xc[(size_t)row * D_INNER + d] = acc * sig;
}

// ---------------- dt = softplus(dbl[:, :16] @ dtW^T + dtb) ----------------
__global__ void dt_k(const float* __restrict__ dbl, const float* __restrict__ dtW,
                     const float* __restrict__ dtb, float* __restrict__ dt)
{
    int idx = blockIdx.x * blockDim.x + threadIdx.x;
    if (idx >= M_ROWS * D_INNER) return;
    int d = idx & (D_INNER - 1);
    int row = idx >> 9;
    const float* r = dbl + (size_t)row * 48;
    const float* w = dtW + d * DT_RANK;
    float s = dtb[d];
#pragma unroll
    for (int j = 0; j < DT_RANK; j++) s = fmaf(r[j], w[j], s);
    float sp = (s > 20.f) ? s : log1pf(__expf(s));
    dt[(size_t)row * D_INNER + d] = sp;
}

// ---------------- selective scan ----------------
// warp = (batch, 8 channels); 4 lanes/channel, 4 states/lane.
// Unroll-by-4 with register prefetch depth 4. FAST path exploits
// A[d][s] == -(s+1)  (verified at runtime) -> 1 exp/lane-step.
struct ScanIn { float dt, xc, z; float4 B, C; };

template<bool FAST>
__device__ __forceinline__ void scan_loop(
    const float* pdt, const float* pxc, const float* pz, const float* pbc,
    float* py, int sg, float a0, float a1, float a2, float a3, float Dd)
{
    float h0 = 0.f, h1 = 0.f, h2 = 0.f, h3 = 0.f;

    ScanIn buf[4];
#pragma unroll
    for (int j = 0; j < 4; j++) {
        buf[j].dt = pdt[(size_t)j * D_INNER];
        buf[j].xc = pxc[(size_t)j * D_INNER];
        buf[j].z  = pz [(size_t)j * (2*D_INNER)];
        buf[j].B  = *(const float4*)(pbc + (size_t)j * 48);
        buf[j].C  = *(const float4*)(pbc + (size_t)j * 48 + D_STATE);
    }

    for (int t = 0; t < SEQ; t += 4) {
#pragma unroll
        for (int j = 0; j < 4; j++) {
            ScanIn cur = buf[j];
            int tn = t + 4 + j;
            if (tn < SEQ) {
                buf[j].dt = pdt[(size_t)tn * D_INNER];
                buf[j].xc = pxc[(size_t)tn * D_INNER];
                buf[j].z  = pz [(size_t)tn * (2*D_INNER)];
                buf[j].B  = *(const float4*)(pbc + (size_t)tn * 48);
                buf[j].C  = *(const float4*)(pbc + (size_t)tn * 48 + D_STATE);
            }
            float u = cur.dt * cur.xc;
            float e0, e1, e2, e3;
            if (FAST) {
                float p  = __expf(-cur.dt);
                float p2 = p * p;
                float p4 = p2 * p2;
                float p8 = p4 * p4;
                float b1 = (sg & 1) ? p4 : 1.f;
                float b2 = (sg & 2) ? p8 : 1.f;
                e0 = b1 * b2 * p;      // p^(4sg+1)
                e1 = e0 * p;
                e2 = e1 * p;
                e3 = e2 * p;
            } else {
                e0 = __expf(cur.dt * a0);
                e1 = __expf(cur.dt * a1);
                e2 = __expf(cur.dt * a2);
                e3 = __expf(cur.dt * a3);
            }
            h0 = fmaf(h0, e0, u * cur.B.x);
            h1 = fmaf(h1, e1, u * cur.B.y);
            h2 = fmaf(h2, e2, u * cur.B.z);
            h3 = fmaf(h3, e3, u * cur.B.w);
            float y = h0 * cur.C.x;
            y = fmaf(h1, cur.C.y, y);
            y = fmaf(h2, cur.C.z, y);
            y = fmaf(h3, cur.C.w, y);
            y += __shfl_xor_sync(0xffffffffu, y, 1);
            y += __shfl_xor_sync(0xffffffffu, y, 2);
            float yy = fmaf(cur.xc, Dd, y);
            float sz = cur.z / (1.f + __expf(-cur.z));
            if (sg == 0) py[(size_t)(t + j) * D_INNER] = yy * sz;
        }
    }
}

__global__ void scan_k(const float* __restrict__ dt, const float* __restrict__ xc,
                       const float* __restrict__ dbl, const float* __restrict__ xz,
                       const float* __restrict__ A_log, const float* __restrict__ Dv,
                       float* __restrict__ yb)
{
    int warp = (blockIdx.x * blockDim.x + threadIdx.x) >> 5;
    int lane = threadIdx.x & 31;
    if (warp >= BATCH * (D_INNER / 8)) return;
    int b = warp >> 6;
    int dgrp = warp & 63;
    int dl = lane >> 2;
    int sg = lane & 3;
    int d = dgrp * 8 + dl;

    const float* pdt = dt  + (size_t)b * SEQ * D_INNER + d;
    const float* pxc = xc  + (size_t)b * SEQ * D_INNER + d;
    const float* pz  = xz  + (size_t)b * SEQ * (2*D_INNER) + D_INNER + d;
    const float* pbc = dbl + (size_t)b * SEQ * 48 + DT_RANK + 4 * sg;
    float* py        = yb  + (size_t)b * SEQ * D_INNER + d;

    float4 al = *(const float4*)(A_log + d * D_STATE + 4 * sg);
    float a0 = -expf(al.x), a1 = -expf(al.y), a2 = -expf(al.z), a3 = -expf(al.w);
    float Dd = Dv[d];

    // runtime structure check: A[d][s] == -(s+1) ?
    float n0 = (float)(4 * sg + 1);
    bool ok = fabsf(a0 + n0)        < 1e-3f * n0 &&
              fabsf(a1 + (n0 + 1)) < 1e-3f * (n0 + 1) &&
              fabsf(a2 + (n0 + 2)) < 1e-3f * (n0 + 2) &&
              fabsf(a3 + (n0 + 3)) < 1e-3f * (n0 + 3);
    bool fast = __all_sync(0xffffffffu, ok);

    if (fast) scan_loop<true >(pdt, pxc, pz, pbc, py, sg, a0, a1, a2, a3, Dd);
    else      scan_loop<false>(pdt, pxc, pz, pbc, py, sg, a0, a1, a2, a3, Dd);
}

// ---------------- host side ----------------
static inline void launch_gemm(const float* A, const float* W, const float* bias,
                               float* C, int M, int N, int K, int ldc, bool acc)
{
    dim3 grid((N + GBN - 1) / GBN, (M + GBM - 1) / GBM);
    if (acc) gemm_tf32<true><<<grid, 256>>>(A, W, bias, C, M, N, K, ldc);
    else     gemm_tf32<false><<<grid, 256>>>(A, W, bias, C, M, N, K, ldc);
}

extern "C" void kernel_launch(void* const* d_in, const int* in_sizes, int n_in,
                              void* d_out, int out_size)
{
    const float* wav    = (const float*)d_in[0];
    const float* lib    = (const float*)d_in[1];
    const float* w2v_W  = (const float*)d_in[2];
    const float* w2v_b  = (const float*)d_in[3];
    const float* lib_W  = (const float*)d_in[4];
    const float* lib_b  = (const float*)d_in[5];
    const float* fuse_W = (const float*)d_in[6];
    const float* fuse_b = (const float*)d_in[7];
    const float* proj_W = (const float*)d_in[8];
    const float* proj_b = (const float*)d_in[9];
    const float* ln_g   = (const float*)d_in[10];
    const float* ln_b   = (const float*)d_in[11];
    const float* in_W   = (const float*)d_in[12];
    const float* conv_W = (const float*)d_in[13];
    const float* conv_b = (const float*)d_in[14];
    const float* xproj_W= (const float*)d_in[15];
    const float* dt_W   = (const float*)d_in[16];
    const float* dt_b   = (const float*)d_in[17];
    const float* A_log  = (const float*)d_in[18];
    const float* D_vec  = (const float*)d_in[19];
    const float* out_W  = (const float*)d_in[20];
    const float* fnorm_g= (const float*)d_in[21];
    const float* fnorm_b= (const float*)d_in[22];
    float* out = (float*)d_out;

    float *wl, *tb, *hb, *xln, *xzb, *xcb, *dblb, *dtb2, *yb;
    cudaGetSymbolAddress((void**)&wl,   g_wl);
    cudaGetSymbolAddress((void**)&tb,   g_t);
    cudaGetSymbolAddress((void**)&hb,   g_h);
    cudaGetSymbolAddress((void**)&xln,  g_xln);
    cudaGetSymbolAddress((void**)&xzb,  g_xz);
    cudaGetSymbolAddress((void**)&xcb,  g_xc);
    cudaGetSymbolAddress((void**)&dblb, g_dbl);
    cudaGetSymbolAddress((void**)&dtb2, g_dt);
    cudaGetSymbolAddress((void**)&yb,   g_y);

    const int M = M_ROWS;

    // frontend
    launch_gemm(wav, w2v_W, w2v_b, wl,           M, D_MODEL, W2V_DIM,   2*D_MODEL, false);
    launch_gemm(lib, lib_W, lib_b, wl + D_MODEL, M, D_MODEL, LIB_DIM,   2*D_MODEL, false);
    launch_gemm(wl,  fuse_W, fuse_b, tb,         M, D_MODEL, 2*D_MODEL, D_MODEL,   false);
    launch_gemm(tb,  proj_W, proj_b, hb,         M, D_MODEL, D_MODEL,   D_MODEL,   false);

    const int EW_BLOCKS = (M_ROWS * D_INNER) / 256;

    for (int i = 0; i < N_LAYERS; i++) {
        const float* lg  = ln_g   + i * D_MODEL;
        const float* lb  = ln_b   + i * D_MODEL;
        const float* iw  = in_W   + (size_t)i * 2*D_INNER * D_MODEL;
        const float* cw  = conv_W + (size_t)i * D_INNER * 4;
        const float* cb  = conv_b + (size_t)i * D_INNER;
        const float* xw  = xproj_W+ (size_t)i * (DT_RANK + 2*D_STATE) * D_INNER;
        const float* dw  = dt_W   + (size_t)i * D_INNER * DT_RANK;
        const float* db  = dt_b   + (size_t)i * D_INNER;
        const float* al  = A_log  + (size_t)i * D_INNER * D_STATE;
        const float* dv  = D_vec  + (size_t)i * D_INNER;
        const float* ow  = out_W  + (size_t)i * D_MODEL * D_INNER;

        ln_k<<<M_ROWS / 8, 256>>>(hb, lg, lb, xln);
        launch_gemm(xln, iw, nullptr, xzb, M, 2*D_INNER, D_MODEL, 2*D_INNER, false);
        conv_k<<<EW_BLOCKS, 256>>>(xzb, cw, cb, xcb);
        launch_gemm(xcb, xw, nullptr, dblb, M, DT_RANK + 2*D_STATE, D_INNER, DT_RANK + 2*D_STATE, false);
        dt_k<<<EW_BLOCKS, 256>>>(dblb, dw, db, dtb2);
        scan_k<<<128, 128>>>(dtb2, xcb, dblb, xzb, al, dv, yb);
        launch_gemm(yb, ow, nullptr, hb, M, D_MODEL, D_INNER, D_MODEL, true);
    }

    ln_k<<<M_ROWS / 8, 256>>>(hb, fnorm_g, fnorm_b, out);
}

// round 3
// speedup vs baseline: 1.7881x; 1.0605x over previous
#include <cuda_runtime.h>
#include <math.h>
#include <stdint.h>

// ---------------- problem constants ----------------
#define BATCH   8
#define SEQ     1024
#define M_ROWS  (BATCH*SEQ)        // 8192
#define D_MODEL 256
#define D_INNER 512
#define D_STATE 16
#define DT_RANK 16
#define N_LAYERS 4
#define W2V_DIM 768
#define LIB_DIM 93
#define NCH     8                  // scan chunks
#define CH      (SEQ/NCH)          // 128

// ---------------- scratch buffers ----------------
__device__ float g_wl [M_ROWS * (2*D_MODEL)];
__device__ float g_t  [M_ROWS * D_MODEL];
__device__ float g_h  [M_ROWS * D_MODEL];
__device__ float g_xln[M_ROWS * D_MODEL];
__device__ float g_xz [M_ROWS * (2*D_INNER)];
__device__ float g_xc [M_ROWS * D_INNER];
__device__ float g_dbl[M_ROWS * (DT_RANK+2*D_STATE)];
__device__ float g_dt [M_ROWS * D_INNER];
__device__ float g_y  [M_ROWS * D_INNER];
__device__ float g_hend [BATCH * NCH * D_INNER * D_STATE];
__device__ float g_pend [BATCH * NCH * D_INNER * D_STATE];
__device__ float g_carry[BATCH * NCH * D_INNER * D_STATE];

// ============================================================
// TF32-split tensor-core GEMM:  C[M,N] = A @ W^T (+bias)(+=C)
// 3-term split (hi*hi + hi*lo + lo*hi) -> ~fp32 precision.
// CTA tile 128x64, BK=16, 8 warps (2m x 4n), warp tile 64x16.
// Dynamic smem, double buffered, 2 CTAs/SM.
// ============================================================
#define GBM 128
#define GBN 64
#define GBK 16
#define GPAD 20

#define SA_SZ (GBM*GPAD)   // 2560 words per buffer
#define SW_SZ (GBN*GPAD)   // 1280 words per buffer
#define SMEM_WORDS (2*SA_SZ*2 + 2*SW_SZ*2)   // hi+lo, 2 buffers = 15360 words

__device__ __forceinline__ uint32_t f2tf(float f) {
    uint32_t u;
    asm("cvt.rna.tf32.f32 %0, %1;" : "=r"(u) : "f"(f));
    return u;
}

__device__ __forceinline__ void mma_tf32(float c[4], uint32_t a0, uint32_t a1,
                                         uint32_t a2, uint32_t a3,
                                         uint32_t b0, uint32_t b1) {
    asm volatile(
        "mma.sync.aligned.m16n8k8.row.col.f32.tf32.tf32.f32 "
        "{%0,%1,%2,%3}, {%4,%5,%6,%7}, {%8,%9}, {%0,%1,%2,%3};"
        : "+f"(c[0]), "+f"(c[1]), "+f"(c[2]), "+f"(c[3])
        : "r"(a0), "r"(a1), "r"(a2), "r"(a3), "r"(b0), "r"(b1));
}

__device__ __forceinline__ void split4(float4 v, uint4& hi, uint4& lo) {
    hi.x = f2tf(v.x); lo.x = f2tf(v.x - __uint_as_float(hi.x));
    hi.y = f2tf(v.y); lo.y = f2tf(v.y - __uint_as_float(hi.y));
    hi.z = f2tf(v.z); lo.z = f2tf(v.z - __uint_as_float(hi.z));
    hi.w = f2tf(v.w); lo.w = f2tf(v.w - __uint_as_float(hi.w));
}

template<bool ACC>
__global__ __launch_bounds__(256, 2)
void gemm_tf32(const float* __restrict__ A, const float* __restrict__ W,
               const float* __restrict__ bias, float* __restrict__ C,
               int M, int N, int K, int ldc)
{
    extern __shared__ uint32_t smem[];
    uint32_t* As_hi = smem;                    // [2][SA_SZ]
    uint32_t* As_lo = smem + 2*SA_SZ;          // [2][SA_SZ]
    uint32_t* Ws_hi = smem + 4*SA_SZ;          // [2][SW_SZ]
    uint32_t* Ws_lo = smem + 4*SA_SZ + 2*SW_SZ;// [2][SW_SZ]

    const int tid  = threadIdx.x;
    const int lane = tid & 31;
    const int g    = lane >> 2;
    const int tg   = lane & 3;
    const int warp = tid >> 5;
    const int wm   = warp >> 2;     // 0..1 (64 rows)
    const int wn   = warp & 3;      // 0..3 (16 cols)
    const int m0   = blockIdx.y * GBM;
    const int n0   = blockIdx.x * GBN;
    const bool k4  = (K & 3) == 0;

    float acc[4][2][4];
#pragma unroll
    for (int i = 0; i < 4; i++)
#pragma unroll
        for (int j = 0; j < 2; j++)
#pragma unroll
            for (int l = 0; l < 4; l++) acc[i][j][l] = 0.f;

    const int ntiles = (K + GBK - 1) / GBK;
    float4 vA[2], vW;

    // A: 128x16 = 512 float4, 2/thread.  W: 64x16 = 256 float4, 1/thread.
    int rowA[2], colA[2];
#pragma unroll
    for (int i = 0; i < 2; i++) {
        int id = tid + i * 256;
        rowA[i] = id >> 2; colA[i] = (id & 3) * 4;
    }
    const int rowW = tid >> 2, colW = (tid & 3) * 4;

    auto loadg = [&](int kt) {
        int k0 = kt * GBK;
#pragma unroll
        for (int i = 0; i < 2; i++) {
            int gm = m0 + rowA[i];
            int gk = k0 + colA[i];
            float4 v = make_float4(0.f, 0.f, 0.f, 0.f);
            const float* p = A + (size_t)gm * K + gk;
            if (k4 && gk + 3 < K) v = *(const float4*)p;
            else {
                if (gk     < K) v.x = p[0];
                if (gk + 1 < K) v.y = p[1];
                if (gk + 2 < K) v.z = p[2];
                if (gk + 3 < K) v.w = p[3];
            }
            vA[i] = v;
        }
        {
            int gn = n0 + rowW;
            int gk = k0 + colW;
            float4 v = make_float4(0.f, 0.f, 0.f, 0.f);
            if (gn < N) {
                const float* p = W + (size_t)gn * K + gk;
                if (k4 && gk + 3 < K) v = *(const float4*)p;
                else {
                    if (gk     < K) v.x = p[0];
                    if (gk + 1 < K) v.y = p[1];
                    if (gk + 2 < K) v.z = p[2];
                    if (gk + 3 < K) v.w = p[3];
                }
            }
            vW = v;
        }
    };
    auto store = [&](int buf) {
        uint4 hi, lo;
#pragma unroll
        for (int i = 0; i < 2; i++) {
            split4(vA[i], hi, lo);
            int off = buf * SA_SZ + rowA[i] * GPAD + colA[i];
            *(uint4*)&As_hi[off] = hi;
            *(uint4*)&As_lo[off] = lo;
        }
        split4(vW, hi, lo);
        int off = buf * SW_SZ + rowW * GPAD + colW;
        *(uint4*)&Ws_hi[off] = hi;
        *(uint4*)&Ws_lo[off] = lo;
    };
    auto compute = [&](int buf) {
#pragma unroll
        for (int ks = 0; ks < 2; ks++) {
            int kk = ks * 8;
            uint32_t ah[4][4], al[4][4], bh[2][2], bl[2][2];
#pragma unroll
            for (int mt = 0; mt < 4; mt++) {
                int r = wm * 64 + mt * 16 + g;
                int o0 = buf * SA_SZ + r * GPAD + kk + tg;
                int o1 = o0 + 8 * GPAD;
                ah[mt][0] = As_hi[o0];     ah[mt][1] = As_hi[o1];
                ah[mt][2] = As_hi[o0 + 4]; ah[mt][3] = As_hi[o1 + 4];
                al[mt][0] = As_lo[o0];     al[mt][1] = As_lo[o1];
                al[mt][2] = As_lo[o0 + 4]; al[mt][3] = As_lo[o1 + 4];
            }
#pragma unroll
            for (int nt = 0; nt < 2; nt++) {
                int c = wn * 16 + nt * 8 + g;
                int o = buf * SW_SZ + c * GPAD + kk + tg;
                bh[nt][0] = Ws_hi[o]; bh[nt][1] = Ws_hi[o + 4];
                bl[nt][0] = Ws_lo[o]; bl[nt][1] = Ws_lo[o + 4];
            }
#pragma unroll
            for (int mt = 0; mt < 4; mt++)
#pragma unroll
                for (int nt = 0; nt < 2; nt++) {
                    mma_tf32(acc[mt][nt], ah[mt][0], ah[mt][1], ah[mt][2], ah[mt][3],
                             bl[nt][0], bl[nt][1]);
                    mma_tf32(acc[mt][nt], al[mt][0], al[mt][1], al[mt][2], al[mt][3],
                             bh[nt][0], bh[nt][1]);
                    mma_tf32(acc[mt][nt], ah[mt][0], ah[mt][1], ah[mt][2], ah[mt][3],
                             bh[nt][0], bh[nt][1]);
                }
        }
    };

    loadg(0);
    store(0);
    __syncthreads();
    for (int kt = 0; kt < ntiles; kt++) {
        int buf = kt & 1;
        if (kt + 1 < ntiles) loadg(kt + 1);
        compute(buf);
        if (kt + 1 < ntiles) {
            store(buf ^ 1);
            __syncthreads();
        }
    }

#pragma unroll
    for (int mt = 0; mt < 4; mt++) {
        int r0 = m0 + wm * 64 + mt * 16 + g;
#pragma unroll
        for (int nt = 0; nt < 2; nt++) {
            int c0 = n0 + wn * 16 + nt * 8 + 2 * tg;
#pragma unroll
            for (int half = 0; half < 2; half++) {
                int r = r0 + half * 8;
#pragma unroll
                for (int jj = 0; jj < 2; jj++) {
                    int c = c0 + jj;
                    if (c < N) {
                        float v = acc[mt][nt][half * 2 + jj];
                        if (bias) v += bias[c];
                        size_t off = (size_t)r * ldc + c;
                        if (ACC) v += C[off];
                        C[off] = v;
                    }
                }
            }
        }
    }
}

// ---------------- layernorm (warp per row of 256) ----------------
__global__ void ln_k(const float* __restrict__ x, const float* __restrict__ g,
                     const float* __restrict__ b, float* __restrict__ y)
{
    int warp = (blockIdx.x * blockDim.x + threadIdx.x) >> 5;
    int lane = threadIdx.x & 31;
    if (warp >= M_ROWS) return;
    const float* xr = x + (size_t)warp * D_MODEL;
    float v[8];
    float s = 0.f, s2 = 0.f;
#pragma unroll
    for (int i = 0; i < 8; i++) {
        v[i] = xr[lane + i * 32];
        s += v[i];
        s2 = fmaf(v[i], v[i], s2);
    }
#pragma unroll
    for (int o = 16; o > 0; o >>= 1) {
        s  += __shfl_xor_sync(0xffffffffu, s,  o);
        s2 += __shfl_xor_sync(0xffffffffu, s2, o);
    }
    float mu = s * (1.f / D_MODEL);
    float var = s2 * (1.f / D_MODEL) - mu * mu;
    float inv = rsqrtf(var + 1e-5f);
    float* yr = y + (size_t)warp * D_MODEL;
#pragma unroll
    for (int i = 0; i < 8; i++) {
        int c = lane + i * 32;
        yr[c] = (v[i] - mu) * inv * g[c] + b[c];
    }
}

// ---------------- causal depthwise conv(4) + silu ----------------
__global__ void conv_k(const float* __restrict__ xz, const float* __restrict__ cw,
                       const float* __restrict__ cb, float* __restrict__ xc)
{
    int idx = blockIdx.x * blockDim.x + threadIdx.x;
    if (idx >= M_ROWS * D_INNER) return;
    int d = idx & (D_INNER - 1);
    int row = idx >> 9;
    int t = row & (SEQ - 1);
    size_t base = (size_t)row * (2*D_INNER) + d;
    float acc = cb[d];
    const float* w = cw + d * 4;
#pragma unroll
    for (int k = 0; k < 4; k++) {
        int tt = t - 3 + k;
        if (tt >= 0) acc = fmaf(xz[base + (size_t)(k - 3) * (2*D_INNER)], w[k], acc);
    }
    float sig = 1.f / (1.f + __expf(-acc));
    xc[(size_t)row * D_INNER + d] = acc * sig;
}

// ---------------- dt = softplus(dbl[:, :16] @ dtW^T + dtb) ----------------
__global__ void dt_k(const float* __restrict__ dbl, const float* __restrict__ dtW,
                     const float* __restrict__ dtb, float* __restrict__ dt)
{
    int idx = blockIdx.x * blockDim.x + threadIdx.x;
    if (idx >= M_ROWS * D_INNER) return;
    int d = idx & (D_INNER - 1);
    int row = idx >> 9;
    const float* r = dbl + (size_t)row * 48;
    const float* w = dtW + d * DT_RANK;
    float s = dtb[d];
#pragma unroll
    for (int j = 0; j < DT_RANK; j++) s = fmaf(r[j], w[j], s);
    float sp = (s > 20.f) ? s : log1pf(__expf(s));
    dt[(size_t)row * D_INNER + d] = sp;
}

// ============================================================
// Chunked selective scan.
// warp = (batch, 8 channels, chunk); 4 lanes/channel, 4 states/lane.
// pass1: local scan (h0=0) -> h_end, P_end per chunk.
// combine: serial fold of NCH chunk carries per (b,d,s).
// pass2: local scan seeded with carry -> y (+gate).
// FAST path: A[d][s] == -(s+1) (runtime-verified) -> 1 exp/step.
// ============================================================

__device__ __forceinline__ void exp_powers(bool FAST, float dtv, int sg,
                                           float a0, float a1, float a2, float a3,
                                           float& e0, float& e1, float& e2, float& e3)
{
    if (FAST) {
        float p  = __expf(-dtv);
        float p2 = p * p;
        float p4 = p2 * p2;
        float p8 = p4 * p4;
        float b1 = (sg & 1) ? p4 : 1.f;
        float b2 = (sg & 2) ? p8 : 1.f;
        e0 = b1 * b2 * p;
        e1 = e0 * p;
        e2 = e1 * p;
        e3 = e2 * p;
    } else {
        e0 = __expf(dtv * a0);
        e1 = __expf(dtv * a1);
        e2 = __expf(dtv * a2);
        e3 = __expf(dtv * a3);
    }
}

__device__ __forceinline__ bool fast_check(const float* A_log, int d, int sg,
                                           float& a0, float& a1, float& a2, float& a3)
{
    float4 al = *(const float4*)(A_log + d * D_STATE + 4 * sg);
    a0 = -expf(al.x); a1 = -expf(al.y); a2 = -expf(al.z); a3 = -expf(al.w);
    float n0 = (float)(4 * sg + 1);
    bool ok = fabsf(a0 + n0)       < 1e-3f * n0 &&
              fabsf(a1 + (n0+1))  < 1e-3f * (n0+1) &&
              fabsf(a2 + (n0+2))  < 1e-3f * (n0+2) &&
              fabsf(a3 + (n0+3))  < 1e-3f * (n0+3);
    return __all_sync(0xffffffffu, ok);
}

template<bool FAST>
__device__ __forceinline__ void p1_body(
    const float* pdt, const float* pxc, const float* pbc,
    int sg, float a0, float a1, float a2, float a3,
    float4& hout, float4& pout)
{
    float h0=0.f,h1=0.f,h2=0.f,h3=0.f;
    float P0=1.f,P1=1.f,P2=1.f,P3=1.f;
    float dbuf[4], xbuf[4]; float4 Bbuf[4];
#pragma unroll
    for (int j = 0; j < 4; j++) {
        dbuf[j] = pdt[(size_t)j * D_INNER];
        xbuf[j] = pxc[(size_t)j * D_INNER];
        Bbuf[j] = *(const float4*)(pbc + (size_t)j * 48);
    }
    for (int t = 0; t < CH; t += 4) {
#pragma unroll
        for (int j = 0; j < 4; j++) {
            float dtv = dbuf[j], xcv = xbuf[j]; float4 B = Bbuf[j];
            int tn = t + 4 + j; if (tn > CH - 1) tn = CH - 1;
            dbuf[j] = pdt[(size_t)tn * D_INNER];
            xbuf[j] = pxc[(size_t)tn * D_INNER];
            Bbuf[j] = *(const float4*)(pbc + (size_t)tn * 48);
            float u = dtv * xcv;
            float e0,e1,e2,e3;
            exp_powers(FAST, dtv, sg, a0,a1,a2,a3, e0,e1,e2,e3);
            h0 = fmaf(h0, e0, u * B.x);  P0 *= e0;
            h1 = fmaf(h1, e1, u * B.y);  P1 *= e1;
            h2 = fmaf(h2, e2, u * B.z);  P2 *= e2;
            h3 = fmaf(h3, e3, u * B.w);  P3 *= e3;
        }
    }
    hout = make_float4(h0,h1,h2,h3);
    pout = make_float4(P0,P1,P2,P3);
}

__global__ void scan_p1(const float* __restrict__ dt, const float* __restrict__ xc,
                        const float* __restrict__ dbl, const float* __restrict__ A_log,
                        float* __restrict__ hend, float* __restrict__ pend)
{
    int warp = (blockIdx.x * blockDim.x + threadIdx.x) >> 5;
    int lane = threadIdx.x & 31;
    int b = warp >> 9;
    int rem = warp & 511;
    int dgrp = rem >> 3;
    int chunk = rem & 7;
    int dl = lane >> 2, sg = lane & 3;
    int d = dgrp * 8 + dl;
    int t0 = chunk * CH;

    const float* pdt = dt  + ((size_t)b * SEQ + t0) * D_INNER + d;
    const float* pxc = xc  + ((size_t)b * SEQ + t0) * D_INNER + d;
    const float* pbc = dbl + ((size_t)b * SEQ + t0) * 48 + DT_RANK + 4 * sg;

    float a0,a1,a2,a3;
    bool fast = fast_check(A_log, d, sg, a0,a1,a2,a3);

    float4 ho, po;
    if (fast) p1_body<true >(pdt, pxc, pbc, sg, a0,a1,a2,a3, ho, po);
    else      p1_body<false>(pdt, pxc, pbc, sg, a0,a1,a2,a3, ho, po);

    size_t base = ((size_t)(b * NCH + chunk) * D_INNER + d) * D_STATE + 4 * sg;
    *(float4*)(hend + base) = ho;
    *(float4*)(pend + base) = po;
}

__global__ void scan_comb(const float* __restrict__ hend, const float* __restrict__ pend,
                          float* __restrict__ carry)
{
    int idx = blockIdx.x * blockDim.x + threadIdx.x;   // 65536
    int b = idx >> 13;
    int r = idx & 8191;
    float c = 0.f;
    carry[(size_t)(b * NCH) * 8192 + r] = 0.f;
    for (int ch = 1; ch < NCH; ch++) {
        size_t prev = (size_t)(b * NCH + ch - 1) * 8192 + r;
        c = fmaf(pend[prev], c, hend[prev]);
        carry[(size_t)(b * NCH + ch) * 8192 + r] = c;
    }
}

template<bool FAST>
__device__ __forceinline__ void p2_body(
    const float* pdt, const float* pxc, const float* pz, const float* pbc,
    float* py, int sg, float a0, float a1, float a2, float a3, float Dd, float4 hin)
{
    float h0=hin.x, h1=hin.y, h2=hin.z, h3=hin.w;
    float dbuf[4], xbuf[4], zbuf[4]; float4 Bbuf[4], Cbuf[4];
#pragma unroll
    for (int j = 0; j < 4; j++) {
        dbuf[j] = pdt[(size_t)j * D_INNER];
        xbuf[j] = pxc[(size_t)j * D_INNER];
        zbuf[j] = pz [(size_t)j * (2*D_INNER)];
        Bbuf[j] = *(const float4*)(pbc + (size_t)j * 48);
        Cbuf[j] = *(const float4*)(pbc + (size_t)j * 48 + D_STATE);
    }
    for (int t = 0; t < CH; t += 4) {
#pragma unroll
        for (int j = 0; j < 4; j++) {
            float dtv = dbuf[j], xcv = xbuf[j], zv = zbuf[j];
            float4 B = Bbuf[j], Cv = Cbuf[j];
            int tn = t + 4 + j; if (tn > CH - 1) tn = CH - 1;
            dbuf[j] = pdt[(size_t)tn * D_INNER];
            xbuf[j] = pxc[(size_t)tn * D_INNER];
            zbuf[j] = pz [(size_t)tn * (2*D_INNER)];
            Bbuf[j] = *(const float4*)(pbc + (size_t)tn * 48);
            Cbuf[j] = *(const float4*)(pbc + (size_t)tn * 48 + D_STATE);
            float u = dtv * xcv;
            float e0,e1,e2,e3;
            exp_powers(FAST, dtv, sg, a0,a1,a2,a3, e0,e1,e2,e3);
            h0 = fmaf(h0, e0, u * B.x);
            h1 = fmaf(h1, e1, u * B.y);
            h2 = fmaf(h2, e2, u * B.z);
            h3 = fmaf(h3, e3, u * B.w);
            float y = h0 * Cv.x;
            y = fmaf(h1, Cv.y, y);
            y = fmaf(h2, Cv.z, y);
            y = fmaf(h3, Cv.w, y);
            y += __shfl_xor_sync(0xffffffffu, y, 1);
            y += __shfl_xor_sync(0xffffffffu, y, 2);
            float yy = fmaf(xcv, Dd, y);
            float sz = zv / (1.f + __expf(-zv));
            if (sg == 0) py[(size_t)(t + j) * D_INNER] = yy * sz;
        }
    }
}

__global__ void scan_p2(const float* __restrict__ dt, const float* __restrict__ xc,
                        const float* __restrict__ dbl, const float* __restrict__ xz,
                        const float* __restrict__ A_log, const float* __restrict__ Dv,
                        const float* __restrict__ carry, float* __restrict__ yb)
{
    int warp = (blockIdx.x * blockDim.x + threadIdx.x) >> 5;
    int lane = threadIdx.x & 31;
    int b = warp >> 9;
    int rem = warp & 511;
    int dgrp = rem >> 3;
    int chunk = rem & 7;
    int dl = lane >> 2, sg = lane & 3;
    int d = dgrp * 8 + dl;
    int t0 = chunk * CH;

    const float* pdt = dt  + ((size_t)b * SEQ + t0) * D_INNER + d;
    const float* pxc = xc  + ((size_t)b * SEQ + t0) * D_INNER + d;
    const float* pz  = xz  + ((size_t)b * SEQ + t0) * (2*D_INNER) + D_INNER + d;
    const float* pbc = dbl + ((size_t)b * SEQ + t0) * 48 + DT_RANK + 4 * sg;
    float* py        = yb  + ((size_t)b * SEQ + t0) * D_INNER + d;

    float a0,a1,a2,a3;
    bool fast = fast_check(A_log, d, sg, a0,a1,a2,a3);
    float Dd = Dv[d];
    float4 hin = *(const float4*)(carry +
        ((size_t)(b * NCH + chunk) * D_INNER + d) * D_STATE + 4 * sg);

    if (fast) p2_body<true >(pdt, pxc, pz, pbc, py, sg, a0,a1,a2,a3, Dd, hin);
    else      p2_body<false>(pdt, pxc, pz, pbc, py, sg, a0,a1,a2,a3, Dd, hin);
}

// ---------------- host side ----------------
static inline void launch_gemm(const float* A, const float* W, const float* bias,
                               float* C, int M, int N, int K, int ldc, bool acc)
{
    dim3 grid((N + GBN - 1) / GBN, (M + GBM - 1) / GBM);
    size_t smem = SMEM_WORDS * sizeof(uint32_t);
    if (acc) gemm_tf32<true><<<grid, 256, smem>>>(A, W, bias, C, M, N, K, ldc);
    else     gemm_tf32<false><<<grid, 256, smem>>>(A, W, bias, C, M, N, K, ldc);
}

extern "C" void kernel_launch(void* const* d_in, const int* in_sizes, int n_in,
                              void* d_out, int out_size)
{
    const float* wav    = (const float*)d_in[0];
    const float* lib    = (const float*)d_in[1];
    const float* w2v_W  = (const float*)d_in[2];
    const float* w2v_b  = (const float*)d_in[3];
    const float* lib_W  = (const float*)d_in[4];
    const float* lib_b  = (const float*)d_in[5];
    const float* fuse_W = (const float*)d_in[6];
    const float* fuse_b = (const float*)d_in[7];
    const float* proj_W = (const float*)d_in[8];
    const float* proj_b = (const float*)d_in[9];
    const float* ln_g   = (const float*)d_in[10];
    const float* ln_b   = (const float*)d_in[11];
    const float* in_W   = (const float*)d_in[12];
    const float* conv_W = (const float*)d_in[13];
    const float* conv_b = (const float*)d_in[14];
    const float* xproj_W= (const float*)d_in[15];
    const float* dt_W   = (const float*)d_in[16];
    const float* dt_b   = (const float*)d_in[17];
    const float* A_log  = (const float*)d_in[18];
    const float* D_vec  = (const float*)d_in[19];
    const float* out_W  = (const float*)d_in[20];
    const float* fnorm_g= (const float*)d_in[21];
    const float* fnorm_b= (const float*)d_in[22];
    float* out = (float*)d_out;

    static int attr_done = 0;
    size_t smem = SMEM_WORDS * sizeof(uint32_t);
    cudaFuncSetAttribute(gemm_tf32<false>, cudaFuncAttributeMaxDynamicSharedMemorySize, (int)smem);
    cudaFuncSetAttribute(gemm_tf32<true>,  cudaFuncAttributeMaxDynamicSharedMemorySize, (int)smem);
    (void)attr_done;

    float *wl, *tb, *hb, *xln, *xzb, *xcb, *dblb, *dtb2, *yb, *he, *pe, *ca;
    cudaGetSymbolAddress((void**)&wl,   g_wl);
    cudaGetSymbolAddress((void**)&tb,   g_t);
    cudaGetSymbolAddress((void**)&hb,   g_h);
    cudaGetSymbolAddress((void**)&xln,  g_xln);
    cudaGetSymbolAddress((void**)&xzb,  g_xz);
    cudaGetSymbolAddress((void**)&xcb,  g_xc);
    cudaGetSymbolAddress((void**)&dblb, g_dbl);
    cudaGetSymbolAddress((void**)&dtb2, g_dt);
    cudaGetSymbolAddress((void**)&yb,   g_y);
    cudaGetSymbolAddress((void**)&he,   g_hend);
    cudaGetSymbolAddress((void**)&pe,   g_pend);
    cudaGetSymbolAddress((void**)&ca,   g_carry);

    const int M = M_ROWS;

    launch_gemm(wav, w2v_W, w2v_b, wl,           M, D_MODEL, W2V_DIM,   2*D_MODEL, false);
    launch_gemm(lib, lib_W, lib_b, wl + D_MODEL, M, D_MODEL, LIB_DIM,   2*D_MODEL, false);
    launch_gemm(wl,  fuse_W, fuse_b, tb,         M, D_MODEL, 2*D_MODEL, D_MODEL,   false);
    launch_gemm(tb,  proj_W, proj_b, hb,         M, D_MODEL, D_MODEL,   D_MODEL,   false);

    const int EW_BLOCKS = (M_ROWS * D_INNER) / 256;
    const int SCAN_BLOCKS = (BATCH * 64 * NCH) / 8;   // 4096 warps / 8 per block

    for (int i = 0; i < N_LAYERS; i++) {
        const float* lg  = ln_g   + i * D_MODEL;
        const float* lb  = ln_b   + i * D_MODEL;
        const float* iw  = in_W   + (size_t)i * 2*D_INNER * D_MODEL;
        const float* cw  = conv_W + (size_t)i * D_INNER * 4;
        const float* cb  = conv_b + (size_t)i * D_INNER;
        const float* xw  = xproj_W+ (size_t)i * (DT_RANK + 2*D_STATE) * D_INNER;
        const float* dw  = dt_W   + (size_t)i * D_INNER * DT_RANK;
        const float* db  = dt_b   + (size_t)i * D_INNER;
        const float* al  = A_log  + (size_t)i * D_INNER * D_STATE;
        const float* dv  = D_vec  + (size_t)i * D_INNER;
        const float* ow  = out_W  + (size_t)i * D_MODEL * D_INNER;

        ln_k<<<M_ROWS / 8, 256>>>(hb, lg, lb, xln);
        launch_gemm(xln, iw, nullptr, xzb, M, 2*D_INNER, D_MODEL, 2*D_INNER, false);
        conv_k<<<EW_BLOCKS, 256>>>(xzb, cw, cb, xcb);
        launch_gemm(xcb, xw, nullptr, dblb, M, DT_RANK + 2*D_STATE, D_INNER, DT_RANK + 2*D_STATE, false);
        dt_k<<<EW_BLOCKS, 256>>>(dblb, dw, db, dtb2);
        scan_p1<<<SCAN_BLOCKS, 256>>>(dtb2, xcb, dblb, al, he, pe);
        scan_comb<<<64, 1024>>>(he, pe, ca);
        scan_p2<<<SCAN_BLOCKS, 256>>>(dtb2, xcb, dblb, xzb, al, dv, ca, yb);
        launch_gemm(yb, ow, nullptr, hb, M, D_MODEL, D_INNER, D_MODEL, true);
    }

    ln_k<<<M_ROWS / 8, 256>>>(hb, fnorm_g, fnorm_b, out);
}